// round 2
// baseline (speedup 1.0000x reference)
#include <cuda_runtime.h>
#include <math.h>

// Problem constants
constexpr int Bn = 4, Tn = 1024, DMn = 1024, Hn = 16, DKn = 64;
constexpr int BT = Bn * Tn;                 // 4096
constexpr int PLANE = BT * DMn;             // 4194304 elements
constexpr int NBH = Bn * Hn;                // 64 heads total

// ---------------- Scratch (device globals; allocation is forbidden) ----------
__device__ float g_Q[PLANE];
__device__ float g_K[PLANE];
__device__ float g_V[PLANE];
__device__ float g_Dre[2][PLANE];           // ping-pong real plane, (B,T,DM) layout
__device__ float g_Dim[2][PLANE];           // ping-pong imag plane
__device__ float g_A[(size_t)NBH * Tn * Tn];// adjacency, 268 MB
__device__ float g_gv[PLANE];               // gate * V, (B,T,DM)
__device__ float g_gate[(size_t)NBH * Tn * DKn]; // fallback gate target

// ---------------- Generic fp32 SGEMM: C = A(MxK) @ B(KxN), row-major ---------
// 64x64 tile, BK=16, 256 threads, 4x4 per thread.
__global__ void sgemm_nn_kernel(const float* __restrict__ A,
                                const float* __restrict__ B,
                                float* __restrict__ C,
                                int M, int N, int K) {
    __shared__ float As[64][17];   // padded: conflict-free column reads
    __shared__ float Bs[16][64];   // float4-aligned rows
    int tid = threadIdx.x;
    int tx = tid & 15, ty = tid >> 4;
    int m0 = blockIdx.y * 64, n0 = blockIdx.x * 64;

    float acc[4][4] = {};
    for (int k0 = 0; k0 < K; k0 += 16) {
        #pragma unroll
        for (int i = 0; i < 4; i++) {
            int l = tid + 256 * i;
            int r = l >> 4, c = l & 15;
            As[r][c] = A[(size_t)(m0 + r) * K + (k0 + c)];
        }
        #pragma unroll
        for (int i = 0; i < 4; i++) {
            int l = tid + 256 * i;
            int r = l >> 6, c = l & 63;
            Bs[r][c] = B[(size_t)(k0 + r) * N + (n0 + c)];
        }
        __syncthreads();
        #pragma unroll
        for (int kk = 0; kk < 16; kk++) {
            float a[4];
            #pragma unroll
            for (int i = 0; i < 4; i++) a[i] = As[ty * 4 + i][kk];
            float4 bv = *(const float4*)&Bs[kk][tx * 4];
            float b[4] = {bv.x, bv.y, bv.z, bv.w};
            #pragma unroll
            for (int i = 0; i < 4; i++)
                #pragma unroll
                for (int j = 0; j < 4; j++)
                    acc[i][j] = fmaf(a[i], b[j], acc[i][j]);
        }
        __syncthreads();
    }
    #pragma unroll
    for (int i = 0; i < 4; i++)
        #pragma unroll
        for (int j = 0; j < 4; j++)
            C[(size_t)(m0 + ty * 4 + i) * N + (n0 + tx * 4 + j)] = acc[i][j];
}

// ---------------- Scores: per head, S = (Q_h @ K_h^T) / 8 -------------------
// Q,K in (B,T,DM) layout; head slice stride DM. Output into g_A[bh].
__global__ void scores_nt_kernel(const float* __restrict__ Q,
                                 const float* __restrict__ Km,
                                 float* __restrict__ Aout) {
    int bh = blockIdx.z;
    int b = bh >> 4, h = bh & 15;
    const float* Ap = Q  + (size_t)b * Tn * DMn + h * DKn; // rows t, cols d (lda=DM)
    const float* Bp = Km + (size_t)b * Tn * DMn + h * DKn; // rows s, cols d
    float* Cp = Aout + (size_t)bh * Tn * Tn;

    __shared__ float As[64][17];
    __shared__ float Bs[16][68];   // 68*4=272 bytes/row: 16B-aligned rows, low conflicts
    int tid = threadIdx.x;
    int tx = tid & 15, ty = tid >> 4;
    int m0 = blockIdx.y * 64, n0 = blockIdx.x * 64;

    float acc[4][4] = {};
    for (int k0 = 0; k0 < DKn; k0 += 16) {
        #pragma unroll
        for (int i = 0; i < 4; i++) {
            int l = tid + 256 * i;
            int r = l >> 4, c = l & 15;
            As[r][c] = Ap[(size_t)(m0 + r) * DMn + (k0 + c)];
        }
        #pragma unroll
        for (int i = 0; i < 4; i++) {
            int l = tid + 256 * i;
            int n = l >> 4, k = l & 15;
            Bs[k][n] = Bp[(size_t)(n0 + n) * DMn + (k0 + k)];
        }
        __syncthreads();
        #pragma unroll
        for (int kk = 0; kk < 16; kk++) {
            float a[4];
            #pragma unroll
            for (int i = 0; i < 4; i++) a[i] = As[ty * 4 + i][kk];
            float4 bv = *(const float4*)&Bs[kk][tx * 4];
            float b[4] = {bv.x, bv.y, bv.z, bv.w};
            #pragma unroll
            for (int i = 0; i < 4; i++)
                #pragma unroll
                for (int j = 0; j < 4; j++)
                    acc[i][j] = fmaf(a[i], b[j], acc[i][j]);
        }
        __syncthreads();
    }
    #pragma unroll
    for (int i = 0; i < 4; i++)
        #pragma unroll
        for (int j = 0; j < 4; j++)
            Cp[(size_t)(m0 + ty * 4 + i) * Tn + (n0 + tx * 4 + j)] = acc[i][j] * 0.125f;
}

// ---------------- Row softmax over last axis of A (65536 rows of 1024) ------
__global__ void softmax_rows_kernel(float* __restrict__ A) {
    float* p = A + (size_t)blockIdx.x * Tn;
    int tid = threadIdx.x;  // 256
    float v[4];
    float mx = -1e30f;
    #pragma unroll
    for (int i = 0; i < 4; i++) { v[i] = p[tid + 256 * i]; mx = fmaxf(mx, v[i]); }

    __shared__ float red[8];
    #pragma unroll
    for (int o = 16; o; o >>= 1) mx = fmaxf(mx, __shfl_xor_sync(0xffffffffu, mx, o));
    if ((tid & 31) == 0) red[tid >> 5] = mx;
    __syncthreads();
    if (tid == 0) {
        float m = red[0];
        #pragma unroll
        for (int i = 1; i < 8; i++) m = fmaxf(m, red[i]);
        red[0] = m;
    }
    __syncthreads();
    mx = red[0];
    __syncthreads();

    float s = 0.f;
    #pragma unroll
    for (int i = 0; i < 4; i++) { v[i] = expf(v[i] - mx); s += v[i]; }
    #pragma unroll
    for (int o = 16; o; o >>= 1) s += __shfl_xor_sync(0xffffffffu, s, o);
    if ((tid & 31) == 0) red[tid >> 5] = s;
    __syncthreads();
    if (tid == 0) {
        float m = 0.f;
        #pragma unroll
        for (int i = 0; i < 8; i++) m += red[i];
        red[0] = m;
    }
    __syncthreads();
    float inv = 1.f / red[0];
    #pragma unroll
    for (int i = 0; i < 4; i++) p[tid + 256 * i] = v[i] * inv;
}

// ---------------- Propagation: Dout = (1-lam)*Din + lam * (A @ Din) ---------
// batch z in [0,128): b = z>>5, h = (z>>1)&15, plane = z&1 (0=re, 1=im).
// A head (1024x1024), Din/Dout head slice in (B,T,DM), ldb = DM.
__global__ void prop_nn_kernel(const float* __restrict__ Abase,
                               const float* __restrict__ DinRe,
                               const float* __restrict__ DinIm,
                               float* __restrict__ DoutRe,
                               float* __restrict__ DoutIm,
                               const float* __restrict__ lam_ptr) {
    int z = blockIdx.z;
    int b = z >> 5, h = (z >> 1) & 15, plane = z & 1;
    const float* Am = Abase + (size_t)(b * Hn + h) * Tn * Tn;
    const float* Din = (plane ? DinIm : DinRe) + (size_t)b * Tn * DMn + h * DKn;
    float* Dout = (plane ? DoutIm : DoutRe) + (size_t)b * Tn * DMn + h * DKn;

    float lam = 1.f / (1.f + expf(-lam_ptr[0]));
    float oml = 1.f - lam;

    __shared__ float As[64][17];
    __shared__ float Bs[16][64];
    int tid = threadIdx.x;
    int tx = tid & 15, ty = tid >> 4;
    int m0 = blockIdx.y * 64;   // N = 64 exactly, single column tile

    float acc[4][4] = {};
    for (int k0 = 0; k0 < Tn; k0 += 16) {
        #pragma unroll
        for (int i = 0; i < 4; i++) {
            int l = tid + 256 * i;
            int r = l >> 4, c = l & 15;
            As[r][c] = Am[(size_t)(m0 + r) * Tn + (k0 + c)];
        }
        #pragma unroll
        for (int i = 0; i < 4; i++) {
            int l = tid + 256 * i;
            int r = l >> 6, c = l & 63;
            Bs[r][c] = Din[(size_t)(k0 + r) * DMn + c];
        }
        __syncthreads();
        #pragma unroll
        for (int kk = 0; kk < 16; kk++) {
            float a[4];
            #pragma unroll
            for (int i = 0; i < 4; i++) a[i] = As[ty * 4 + i][kk];
            float4 bv = *(const float4*)&Bs[kk][tx * 4];
            float b2[4] = {bv.x, bv.y, bv.z, bv.w};
            #pragma unroll
            for (int i = 0; i < 4; i++)
                #pragma unroll
                for (int j = 0; j < 4; j++)
                    acc[i][j] = fmaf(a[i], b2[j], acc[i][j]);
        }
        __syncthreads();
    }
    #pragma unroll
    for (int i = 0; i < 4; i++) {
        int row = m0 + ty * 4 + i;
        #pragma unroll
        for (int j = 0; j < 4; j++) {
            int col = tx * 4 + j;
            float din = Din[(size_t)row * DMn + col];
            Dout[(size_t)row * DMn + col] = oml * din + lam * acc[i][j];
        }
    }
}

// ---------------- Readout: mean field, gate softmax over T, gated V ---------
// One block per (b,h). 256 threads: d = tid&63, group g = tid>>6 strides t.
__global__ void readout_kernel(const float* __restrict__ Dre,
                               const float* __restrict__ Dim,
                               const float* __restrict__ V,
                               float* __restrict__ gate,
                               float* __restrict__ gv) {
    int bh = blockIdx.x;
    int b = bh >> 4, h = bh & 15;
    const size_t base = (size_t)b * Tn * DMn + h * DKn;
    int tid = threadIdx.x;
    int d = tid & 63, g = tid >> 6;

    __shared__ float s_a[4][64], s_b[4][64];
    __shared__ float s_mre[64], s_mim[64], s_mn[64];

    // 1. mean over T
    float sre = 0.f, sim = 0.f;
    for (int t = g; t < Tn; t += 4) {
        size_t idx = base + (size_t)t * DMn + d;
        sre += Dre[idx];
        sim += Dim[idx];
    }
    s_a[g][d] = sre; s_b[g][d] = sim;
    __syncthreads();
    if (g == 0) {
        float mre = (s_a[0][d] + s_a[1][d] + s_a[2][d] + s_a[3][d]) * (1.f / Tn);
        float mim = (s_b[0][d] + s_b[1][d] + s_b[2][d] + s_b[3][d]) * (1.f / Tn);
        s_mre[d] = mre; s_mim[d] = mim;
        s_mn[d] = sqrtf(mre * mre + mim * mim);
    }
    __syncthreads();
    float mre = s_mre[d], mim = s_mim[d], mn = s_mn[d];

    // 2. column max of cosine score
    float mx = -1e30f;
    for (int t = g; t < Tn; t += 4) {
        size_t idx = base + (size_t)t * DMn + d;
        float re = Dre[idx], im = Dim[idx];
        float dot = re * mre + im * mim;
        float nrm = sqrtf(re * re + im * im) * mn + 1e-8f;
        mx = fmaxf(mx, dot / nrm);
    }
    __syncthreads();
    s_a[g][d] = mx;
    __syncthreads();
    float cmx = fmaxf(fmaxf(s_a[0][d], s_a[1][d]), fmaxf(s_a[2][d], s_a[3][d]));
    __syncthreads();

    // 3. column sum of exp
    float ssum = 0.f;
    for (int t = g; t < Tn; t += 4) {
        size_t idx = base + (size_t)t * DMn + d;
        float re = Dre[idx], im = Dim[idx];
        float dot = re * mre + im * mim;
        float nrm = sqrtf(re * re + im * im) * mn + 1e-8f;
        ssum += expf(dot / nrm - cmx);
    }
    s_a[g][d] = ssum;
    __syncthreads();
    float csum = s_a[0][d] + s_a[1][d] + s_a[2][d] + s_a[3][d];
    float inv = 1.f / csum;

    // 4. gate + gated V
    for (int t = g; t < Tn; t += 4) {
        size_t idx = base + (size_t)t * DMn + d;
        float re = Dre[idx], im = Dim[idx];
        float dot = re * mre + im * mim;
        float nrm = sqrtf(re * re + im * im) * mn + 1e-8f;
        float gt = expf(dot / nrm - cmx) * inv;
        gate[((size_t)bh * Tn + t) * DKn + d] = gt;
        gv[idx] = gt * V[idx];
    }
}

// ---------------- Launch -----------------------------------------------------
extern "C" void kernel_launch(void* const* d_in, const int* in_sizes, int n_in,
                              void* d_out, int out_size) {
    const float* x    = (const float*)d_in[0];
    const float* W_Q  = (const float*)d_in[1];
    const float* W_K  = (const float*)d_in[2];
    const float* W_re = (const float*)d_in[3];
    const float* W_im = (const float*)d_in[4];
    const float* W_V  = (const float*)d_in[5];
    const float* W_O  = (const float*)d_in[6];
    const float* lam  = (const float*)d_in[7];

    float *Q, *Kb, *V, *DreB, *DimB, *Ab, *gv, *gateScratch;
    cudaGetSymbolAddress((void**)&Q, g_Q);
    cudaGetSymbolAddress((void**)&Kb, g_K);
    cudaGetSymbolAddress((void**)&V, g_V);
    cudaGetSymbolAddress((void**)&DreB, g_Dre);
    cudaGetSymbolAddress((void**)&DimB, g_Dim);
    cudaGetSymbolAddress((void**)&Ab, g_A);
    cudaGetSymbolAddress((void**)&gv, g_gv);
    cudaGetSymbolAddress((void**)&gateScratch, g_gate);

    float* Dre0 = DreB;           float* Dre1 = DreB + PLANE;
    float* Dim0 = DimB;           float* Dim1 = DimB + PLANE;

    float* out = (float*)d_out;
    float* gate_dst = (out_size >= 2 * PLANE) ? out + PLANE : gateScratch;

    dim3 thr(256);
    dim3 gemm_grid(DMn / 64, BT / 64);   // (16, 64)

    // Projections
    sgemm_nn_kernel<<<gemm_grid, thr>>>(x, W_Q,  Q,     BT, DMn, DMn);
    sgemm_nn_kernel<<<gemm_grid, thr>>>(x, W_K,  Kb,    BT, DMn, DMn);
    sgemm_nn_kernel<<<gemm_grid, thr>>>(x, W_re, Dre0,  BT, DMn, DMn);
    sgemm_nn_kernel<<<gemm_grid, thr>>>(x, W_im, Dim0,  BT, DMn, DMn);
    sgemm_nn_kernel<<<gemm_grid, thr>>>(x, W_V,  V,     BT, DMn, DMn);

    // Adjacency
    scores_nt_kernel<<<dim3(Tn / 64, Tn / 64, NBH), thr>>>(Q, Kb, Ab);
    softmax_rows_kernel<<<NBH * Tn, thr>>>(Ab);

    // Topology propagation (3 steps, ping-pong)
    dim3 prop_grid(1, Tn / 64, NBH * 2);   // (1, 16, 128)
    prop_nn_kernel<<<prop_grid, thr>>>(Ab, Dre0, Dim0, Dre1, Dim1, lam);
    prop_nn_kernel<<<prop_grid, thr>>>(Ab, Dre1, Dim1, Dre0, Dim0, lam);
    prop_nn_kernel<<<prop_grid, thr>>>(Ab, Dre0, Dim0, Dre1, Dim1, lam);

    // Collapse readout + gating
    readout_kernel<<<NBH, thr>>>(Dre1, Dim1, V, gate_dst, gv);

    // Output projection
    sgemm_nn_kernel<<<gemm_grid, thr>>>(gv, W_O, out, BT, DMn, DMn);
}

// round 4
// speedup vs baseline: 3.7967x; 3.7967x over previous
#include <cuda_runtime.h>
#include <cuda_bf16.h>
#include <math.h>
#include <stdint.h>

constexpr int Bn=4, Tn=1024, DMn=1024, Hn=16, DKn=64;
constexpr int BT=Bn*Tn, PLANE=BT*DMn, NBH=Bn*Hn;
constexpr size_t SSZ=(size_t)NBH*Tn*Tn;
constexpr int DT_BH=128*Tn, VT_BH=64*Tn;
constexpr int DSMEM=81920;             // 2 stages x (4 planes x 128 rows x 80B)
constexpr int PSTR=40;                 // smem row stride in bf16 (80B)
constexpr int PSZ=128*80;              // plane bytes = 10240
constexpr int STG=4*PSZ;               // stage bytes = 40960

// ---- scratch ----
__device__ __nv_bfloat16 g_xHi[PLANE], g_xLo[PLANE];
__device__ __nv_bfloat16 g_WHi[6][DMn*DMn], g_WLo[6][DMn*DMn];   // W^T split [n][k]
__device__ __nv_bfloat16 g_QHi[PLANE], g_QLo[PLANE], g_KHi[PLANE], g_KLo[PLANE];
__device__ float g_S[SSZ];
__device__ __nv_bfloat16 g_AHi[SSZ], g_ALo[SSZ];
__device__ float        g_DtF [2][(size_t)NBH*DT_BH];
__device__ __nv_bfloat16 g_DtHi[2][(size_t)NBH*DT_BH], g_DtLo[2][(size_t)NBH*DT_BH];
__device__ float g_VT[(size_t)NBH*VT_BH], g_gvT[(size_t)NBH*VT_BH], g_gateT[(size_t)NBH*VT_BH];
__device__ __nv_bfloat16 g_gvHi[PLANE], g_gvLo[PLANE];
__device__ float g_gateS[(size_t)NBH*Tn*DKn];

// ---- helpers ----
__device__ __forceinline__ uint32_t smem_u32(const void* p){
    uint32_t a; asm("{ .reg .u64 t; cvta.to.shared.u64 t, %1; cvt.u32.u64 %0, t; }":"=r"(a):"l"(p)); return a;
}
__device__ __forceinline__ void cp16(uint32_t s, const void* g){
    asm volatile("cp.async.cg.shared.global [%0], [%1], 16;"::"r"(s),"l"(__cvta_generic_to_global(g)):"memory");
}
#define CP_COMMIT() asm volatile("cp.async.commit_group;":::"memory")
#define CP_WAIT1()  asm volatile("cp.async.wait_group 1;":::"memory")
#define CP_WAIT0()  asm volatile("cp.async.wait_group 0;":::"memory")
#define LDM_X4(r,a) asm volatile("ldmatrix.sync.aligned.m8n8.x4.shared.b16 {%0,%1,%2,%3}, [%4];" \
    : "=r"((r)[0]),"=r"((r)[1]),"=r"((r)[2]),"=r"((r)[3]) : "r"(a))
__device__ __forceinline__ void mma16816(float* c, const uint32_t* a, uint32_t b0, uint32_t b1){
    asm volatile("mma.sync.aligned.m16n8k16.row.col.f32.bf16.bf16.f32 "
        "{%0,%1,%2,%3}, {%4,%5,%6,%7}, {%8,%9}, {%0,%1,%2,%3};"
        : "+f"(c[0]),"+f"(c[1]),"+f"(c[2]),"+f"(c[3])
        : "r"(a[0]),"r"(a[1]),"r"(a[2]),"r"(a[3]),"r"(b0),"r"(b1));
}

// load one 128x32 bf16 plane (gmem ld elems) into padded smem
__device__ __forceinline__ void load_plane(uint32_t s, const __nv_bfloat16* g, int ld, int tid){
#pragma unroll
    for(int i=0;i<2;i++){
        int idx=tid+(i<<8), row=idx>>2, seg=idx&3;
        cp16(s+row*80+seg*16, g+(size_t)row*ld+seg*8);
    }
}
__device__ __forceinline__ void load_chunk(uint32_t sb,
    const __nv_bfloat16* aHi,const __nv_bfloat16* aLo,int lda,
    const __nv_bfloat16* bHi,const __nv_bfloat16* bLo,int ldb,int c,int tid){
    size_t ko=(size_t)c*32;
    load_plane(sb,        aHi+ko, lda, tid);
    load_plane(sb+PSZ,    aLo+ko, lda, tid);
    load_plane(sb+2*PSZ,  bHi+ko, ldb, tid);
    load_plane(sb+3*PSZ,  bLo+ko, ldb, tid);
}

__device__ __forceinline__ void compute_stage(uint32_t sb,int wm,int wn,int lane,float acc[2][8][4]){
#pragma unroll
    for(int kk=0;kk<32;kk+=16){
        uint32_t a_hi[2][4], a_lo[2][4];
#pragma unroll
        for(int mi=0;mi<2;mi++){
            uint32_t ad=sb+(uint32_t)((wm*32+mi*16+(lane&15))*80+(kk+((lane>>4)<<3))*2);
            LDM_X4(a_hi[mi],ad); LDM_X4(a_lo[mi],ad+PSZ);
        }
#pragma unroll
        for(int np=0;np<4;np++){
            uint32_t bd=sb+2*PSZ+(uint32_t)((wn*64+np*16+(lane&7)+((lane>>4)<<3))*80+(kk+((lane>>3)&1)*8)*2);
            uint32_t bh[4], bl[4];
            LDM_X4(bh,bd); LDM_X4(bl,bd+PSZ);
#pragma unroll
            for(int mi=0;mi<2;mi++)
#pragma unroll
                for(int j=0;j<2;j++){
                    float* c=acc[mi][np*2+j];
                    mma16816(c,a_hi[mi],bh[2*j],bh[2*j+1]);
                    mma16816(c,a_hi[mi],bl[2*j],bl[2*j+1]);
                    mma16816(c,a_lo[mi],bh[2*j],bh[2*j+1]);
                }
        }
    }
}

// C[128,128] tile: A[M][K] hi/lo (lda), B[n][k] hi/lo (ldb), K = 32*nchunks
__device__ __forceinline__ void gemm128(uint32_t dsm_u32,
    const __nv_bfloat16* aHi,const __nv_bfloat16* aLo,int lda,
    const __nv_bfloat16* bHi,const __nv_bfloat16* bLo,int ldb,
    int nchunks, float acc[2][8][4]){
    int tid=threadIdx.x, lane=tid&31, wid=tid>>5, wm=wid>>1, wn=wid&1;
    load_chunk(dsm_u32, aHi,aLo,lda, bHi,bLo,ldb, 0, tid); CP_COMMIT();
    for(int c=0;c<nchunks;c++){
        if(c+1<nchunks){
            load_chunk(dsm_u32+((c+1)&1)*STG, aHi,aLo,lda, bHi,bLo,ldb, c+1, tid);
            CP_COMMIT(); CP_WAIT1();
        } else CP_WAIT0();
        __syncthreads();
        compute_stage(dsm_u32+(c&1)*STG, wm, wn, lane, acc);
        __syncthreads();
    }
}

// ---- projections: C[4096,1024]=x@W^T. mode0 fp32; mode1 split; mode2 Dt(fp32+split); mode3 VT fp32
__global__ void __launch_bounds__(256,2)
proj_kernel(const __nv_bfloat16* __restrict__ aHi,const __nv_bfloat16* __restrict__ aLo,
            const __nv_bfloat16* __restrict__ wHi,const __nv_bfloat16* __restrict__ wLo,
            int mode,int rowoff,float* __restrict__ oF,
            __nv_bfloat16* __restrict__ oHi,__nv_bfloat16* __restrict__ oLo){
    extern __shared__ char dsm[];
    float acc[2][8][4]={};
    int m0=blockIdx.y*128, n0=blockIdx.x*128;
    gemm128(smem_u32(dsm), aHi+(size_t)m0*1024, aLo+(size_t)m0*1024,1024,
            wHi+(size_t)n0*1024, wLo+(size_t)n0*1024,1024, 32, acc);
    int tid=threadIdx.x, lane=tid&31, wid=tid>>5, wm=wid>>1, wn=wid&1, g=lane>>2, tg=lane&3;
#pragma unroll
    for(int mi=0;mi<2;mi++)
#pragma unroll
    for(int ni=0;ni<8;ni++){
        float* a4=acc[mi][ni];
        int cl=n0+wn*64+ni*8+tg*2;
#pragma unroll
        for(int p=0;p<2;p++){
            int row=m0+wm*32+mi*16+g+p*8;
            float v0=a4[2*p], v1=a4[2*p+1];
            if(mode==0){
                *(float2*)&oF[(size_t)row*1024+cl]=make_float2(v0,v1);
            } else if(mode==1){
                size_t dst=(size_t)row*1024+cl;
                __nv_bfloat16 h0=__float2bfloat16(v0), h1=__float2bfloat16(v1);
                *(__nv_bfloat162*)&oHi[dst]=__nv_bfloat162(h0,h1);
                *(__nv_bfloat162*)&oLo[dst]=__nv_bfloat162(
                    __float2bfloat16(v0-__bfloat162float(h0)),
                    __float2bfloat16(v1-__bfloat162float(h1)));
            } else {
                int b=row>>10, t=row&1023, h=cl>>6, d=cl&63, bh=b*16+h;
                if(mode==2){
                    size_t o0=(size_t)bh*DT_BH+(size_t)(rowoff+d)*1024+t;
                    oF[o0]=v0; oF[o0+1024]=v1;
                    __nv_bfloat16 h0=__float2bfloat16(v0), h1=__float2bfloat16(v1);
                    oHi[o0]=h0; oHi[o0+1024]=h1;
                    oLo[o0]=__float2bfloat16(v0-__bfloat162float(h0));
                    oLo[o0+1024]=__float2bfloat16(v1-__bfloat162float(h1));
                } else {
                    size_t o0=(size_t)bh*VT_BH+(size_t)d*1024+t;
                    oF[o0]=v0; oF[o0+1024]=v1;
                }
            }
        }
    }
}

// ---- scores: S[bh][t][s]=Q.K/8 ----
__global__ void __launch_bounds__(256,2)
scores_kernel(const __nv_bfloat16* __restrict__ qHi,const __nv_bfloat16* __restrict__ qLo,
              const __nv_bfloat16* __restrict__ kHi,const __nv_bfloat16* __restrict__ kLo,
              float* __restrict__ S){
    extern __shared__ char dsm[];
    float acc[2][8][4]={};
    int n0=blockIdx.x*128, m0=blockIdx.y*128, bh=blockIdx.z, b=bh>>4, h=bh&15;
    size_t ao=(size_t)(b*1024+m0)*1024+h*64, bo=(size_t)(b*1024+n0)*1024+h*64;
    gemm128(smem_u32(dsm), qHi+ao,qLo+ao,1024, kHi+bo,kLo+bo,1024, 2, acc);
    float* Sb=S+(size_t)bh*Tn*Tn;
    int tid=threadIdx.x, lane=tid&31, wid=tid>>5, wm=wid>>1, wn=wid&1, g=lane>>2, tg=lane&3;
#pragma unroll
    for(int mi=0;mi<2;mi++)
#pragma unroll
    for(int ni=0;ni<8;ni++){
        float* a4=acc[mi][ni];
        int cl=n0+wn*64+ni*8+tg*2;
#pragma unroll
        for(int p=0;p<2;p++){
            int row=m0+wm*32+mi*16+g+p*8;
            *(float2*)&Sb[(size_t)row*1024+cl]=make_float2(a4[2*p]*0.125f,a4[2*p+1]*0.125f);
        }
    }
}

// ---- propagation: Dt_out=(1-lam)Dt_in + lam*(Dt_in@A^T) ----
__global__ void __launch_bounds__(256,2)
prop_kernel(const __nv_bfloat16* __restrict__ dHi,const __nv_bfloat16* __restrict__ dLo,
            const float* __restrict__ dF,
            const __nv_bfloat16* __restrict__ adjHi,const __nv_bfloat16* __restrict__ adjLo,
            float* __restrict__ outF,__nv_bfloat16* __restrict__ outHi,__nv_bfloat16* __restrict__ outLo,
            const float* __restrict__ lam_ptr){
    extern __shared__ char dsm[];
    float acc[2][8][4]={};
    int n0=blockIdx.x*128, bh=blockIdx.y;
    size_t ab=(size_t)bh*DT_BH, bb=(size_t)bh*Tn*Tn+(size_t)n0*1024;
    gemm128(smem_u32(dsm), dHi+ab,dLo+ab,1024, adjHi+bb,adjLo+bb,1024, 32, acc);
    float lam=1.f/(1.f+expf(-lam_ptr[0])), oml=1.f-lam;
    int tid=threadIdx.x, lane=tid&31, wid=tid>>5, wm=wid>>1, wn=wid&1, g=lane>>2, tg=lane&3;
#pragma unroll
    for(int mi=0;mi<2;mi++)
#pragma unroll
    for(int ni=0;ni<8;ni++){
        float* a4=acc[mi][ni];
        int cl=n0+wn*64+ni*8+tg*2;
#pragma unroll
        for(int p=0;p<2;p++){
            int r=wm*32+mi*16+g+p*8;
            size_t off=ab+(size_t)r*1024+cl;
            float2 din=*(const float2*)&dF[off];
            float v0=oml*din.x+lam*a4[2*p], v1=oml*din.y+lam*a4[2*p+1];
            *(float2*)&outF[off]=make_float2(v0,v1);
            __nv_bfloat16 h0=__float2bfloat16(v0), h1=__float2bfloat16(v1);
            *(__nv_bfloat162*)&outHi[off]=__nv_bfloat162(h0,h1);
            *(__nv_bfloat162*)&outLo[off]=__nv_bfloat162(
                __float2bfloat16(v0-__bfloat162float(h0)),
                __float2bfloat16(v1-__bfloat162float(h1)));
        }
    }
}

// ---- row softmax: S -> split-bf16 adjacency ----
__global__ void softmax_rows_kernel(const float* __restrict__ S,
                                    __nv_bfloat16* __restrict__ aHi,__nv_bfloat16* __restrict__ aLo){
    size_t base=(size_t)blockIdx.x*Tn;
    const float* p=S+base; int tid=threadIdx.x;
    float v[4], mx=-1e30f;
#pragma unroll
    for(int i=0;i<4;i++){ v[i]=p[tid+256*i]; mx=fmaxf(mx,v[i]); }
    __shared__ float red[8];
#pragma unroll
    for(int o=16;o;o>>=1) mx=fmaxf(mx,__shfl_xor_sync(0xffffffffu,mx,o));
    if((tid&31)==0) red[tid>>5]=mx;
    __syncthreads();
    if(tid==0){ float m=red[0]; for(int i=1;i<8;i++) m=fmaxf(m,red[i]); red[0]=m; }
    __syncthreads(); mx=red[0]; __syncthreads();
    float s=0.f;
#pragma unroll
    for(int i=0;i<4;i++){ v[i]=expf(v[i]-mx); s+=v[i]; }
#pragma unroll
    for(int o=16;o;o>>=1) s+=__shfl_xor_sync(0xffffffffu,s,o);
    if((tid&31)==0) red[tid>>5]=s;
    __syncthreads();
    if(tid==0){ float m=0.f; for(int i=0;i<8;i++) m+=red[i]; red[0]=m; }
    __syncthreads();
    float inv=1.f/red[0];
#pragma unroll
    for(int i=0;i<4;i++){
        float a=v[i]*inv; __nv_bfloat16 h=__float2bfloat16(a);
        aHi[base+tid+256*i]=h; aLo[base+tid+256*i]=__float2bfloat16(a-__bfloat162float(h));
    }
}

// ---- readout in Dt space ----
__global__ void __launch_bounds__(256)
readout_kernel(const float* __restrict__ DtF,const float* __restrict__ VT,
               float* __restrict__ gateT,float* __restrict__ gvT){
    int bh=blockIdx.x, w=threadIdx.x>>5, lane=threadIdx.x&31;
    const float* base=DtF+(size_t)bh*DT_BH;
    const float* vb=VT+(size_t)bh*VT_BH;
    for(int j=0;j<8;j++){
        int d=w*8+j;
        const float* rRe=base+(size_t)d*1024;
        const float* rIm=base+(size_t)(64+d)*1024;
        float sre=0.f,sim=0.f;
        for(int t=lane;t<1024;t+=32){ sre+=rRe[t]; sim+=rIm[t]; }
#pragma unroll
        for(int o=16;o;o>>=1){ sre+=__shfl_xor_sync(0xffffffffu,sre,o); sim+=__shfl_xor_sync(0xffffffffu,sim,o); }
        float mre=sre*(1.f/1024.f), mim=sim*(1.f/1024.f);
        float mn=sqrtf(mre*mre+mim*mim);
        float mx=-1e30f;
        for(int t=lane;t<1024;t+=32){
            float re=rRe[t], im=rIm[t];
            mx=fmaxf(mx,(re*mre+im*mim)/(sqrtf(re*re+im*im)*mn+1e-8f));
        }
#pragma unroll
        for(int o=16;o;o>>=1) mx=fmaxf(mx,__shfl_xor_sync(0xffffffffu,mx,o));
        float ss=0.f;
        for(int t=lane;t<1024;t+=32){
            float re=rRe[t], im=rIm[t];
            ss+=expf((re*mre+im*mim)/(sqrtf(re*re+im*im)*mn+1e-8f)-mx);
        }
#pragma unroll
        for(int o=16;o;o>>=1) ss+=__shfl_xor_sync(0xffffffffu,ss,o);
        float inv=1.f/ss;
        size_t ob=(size_t)bh*VT_BH+(size_t)d*1024;
        for(int t=lane;t<1024;t+=32){
            float re=rRe[t], im=rIm[t];
            float gt=expf((re*mre+im*mim)/(sqrtf(re*re+im*im)*mn+1e-8f)-mx)*inv;
            gateT[ob+t]=gt; gvT[ob+t]=gt*vb[(size_t)d*1024+t];
        }
    }
}

// ---- gather: gvT,gateT -> gv split (B,T,DM) + gate (B,H,T,DK) ----
__global__ void gather_kernel(const float* __restrict__ gvT,const float* __restrict__ gateT,
                              __nv_bfloat16* __restrict__ gvHi,__nv_bfloat16* __restrict__ gvLo,
                              float* __restrict__ gate){
    __shared__ float tv[32][33], tg2[32][33];
    int bh=blockIdx.z, b=bh>>4, h=bh&15;
    int t0=blockIdx.x*32, d0=blockIdx.y*32;
    int lx=threadIdx.x&31, ly=threadIdx.x>>5;
    for(int i=0;i<32;i+=8){
        size_t src=(size_t)bh*VT_BH+(size_t)(d0+ly+i)*1024+t0+lx;
        tv[ly+i][lx]=gvT[src]; tg2[ly+i][lx]=gateT[src];
    }
    __syncthreads();
    for(int i=0;i<32;i+=8){
        int t=t0+ly+i;
        float v=tv[lx][ly+i], gg=tg2[lx][ly+i];
        size_t po=(size_t)(b*1024+t)*1024+h*64+d0+lx;
        __nv_bfloat16 hh=__float2bfloat16(v);
        gvHi[po]=hh; gvLo[po]=__float2bfloat16(v-__bfloat162float(hh));
        gate[((size_t)bh*1024+t)*64+d0+lx]=gg;
    }
}

__global__ void split_kernel(const float* __restrict__ x,__nv_bfloat16* __restrict__ hi,
                             __nv_bfloat16* __restrict__ lo,int n){
    int i=blockIdx.x*256+threadIdx.x;
    for(; i<n; i+=gridDim.x*256){
        float v=x[i]; __nv_bfloat16 h=__float2bfloat16(v);
        hi[i]=h; lo[i]=__float2bfloat16(v-__bfloat162float(h));
    }
}
__global__ void split_wt_kernel(const float* __restrict__ W,__nv_bfloat16* __restrict__ hi,
                                __nv_bfloat16* __restrict__ lo){
    __shared__ float ts[32][33];
    int k0=blockIdx.y*32, n0=blockIdx.x*32;
    int lx=threadIdx.x&31, ly=threadIdx.x>>5;
    for(int i=0;i<32;i+=8) ts[ly+i][lx]=W[(size_t)(k0+ly+i)*1024+n0+lx];
    __syncthreads();
    for(int i=0;i<32;i+=8){
        float v=ts[lx][ly+i];
        size_t dst=(size_t)(n0+ly+i)*1024+k0+lx;
        __nv_bfloat16 h=__float2bfloat16(v);
        hi[dst]=h; lo[dst]=__float2bfloat16(v-__bfloat162float(h));
    }
}

extern "C" void kernel_launch(void* const* d_in,const int* in_sizes,int n_in,
                              void* d_out,int out_size){
    const float* x=(const float*)d_in[0];
    const float* W[6]={(const float*)d_in[1],(const float*)d_in[2],(const float*)d_in[3],
                       (const float*)d_in[4],(const float*)d_in[5],(const float*)d_in[6]};
    const float* lam=(const float*)d_in[7];

    __nv_bfloat16 *xHi,*xLo,*WHi,*WLo,*QHi,*QLo,*KHi,*KLo,*AHi,*ALo,*DtHi,*DtLo,*gvHi,*gvLo;
    float *S,*DtF,*VT,*gvT,*gateT,*gateS;
    cudaGetSymbolAddress((void**)&xHi,g_xHi);   cudaGetSymbolAddress((void**)&xLo,g_xLo);
    cudaGetSymbolAddress((void**)&WHi,g_WHi);   cudaGetSymbolAddress((void**)&WLo,g_WLo);
    cudaGetSymbolAddress((void**)&QHi,g_QHi);   cudaGetSymbolAddress((void**)&QLo,g_QLo);
    cudaGetSymbolAddress((void**)&KHi,g_KHi);   cudaGetSymbolAddress((void**)&KLo,g_KLo);
    cudaGetSymbolAddress((void**)&AHi,g_AHi);   cudaGetSymbolAddress((void**)&ALo,g_ALo);
    cudaGetSymbolAddress((void**)&S,g_S);
    cudaGetSymbolAddress((void**)&DtF,g_DtF);   cudaGetSymbolAddress((void**)&DtHi,g_DtHi);
    cudaGetSymbolAddress((void**)&DtLo,g_DtLo);
    cudaGetSymbolAddress((void**)&VT,g_VT);     cudaGetSymbolAddress((void**)&gvT,g_gvT);
    cudaGetSymbolAddress((void**)&gateT,g_gateT);
    cudaGetSymbolAddress((void**)&gvHi,g_gvHi); cudaGetSymbolAddress((void**)&gvLo,g_gvLo);
    cudaGetSymbolAddress((void**)&gateS,g_gateS);

    const size_t DTSZ=(size_t)NBH*DT_BH, WSZ=(size_t)DMn*DMn;
    float* out=(float*)d_out;
    float* gate_dst=(out_size>=2*PLANE)? out+PLANE : gateS;

    cudaFuncSetAttribute(proj_kernel,  cudaFuncAttributeMaxDynamicSharedMemorySize,DSMEM);
    cudaFuncSetAttribute(scores_kernel,cudaFuncAttributeMaxDynamicSharedMemorySize,DSMEM);
    cudaFuncSetAttribute(prop_kernel,  cudaFuncAttributeMaxDynamicSharedMemorySize,DSMEM);

    split_kernel<<<2048,256>>>(x,xHi,xLo,PLANE);
    for(int w=0;w<6;w++)
        split_wt_kernel<<<dim3(32,32),256>>>(W[w],WHi+w*WSZ,WLo+w*WSZ);

    dim3 thr(256), pgrid(8,32);
    proj_kernel<<<pgrid,thr,DSMEM>>>(xHi,xLo,WHi+0*WSZ,WLo+0*WSZ,1,0,nullptr,QHi,QLo);
    proj_kernel<<<pgrid,thr,DSMEM>>>(xHi,xLo,WHi+1*WSZ,WLo+1*WSZ,1,0,nullptr,KHi,KLo);
    proj_kernel<<<pgrid,thr,DSMEM>>>(xHi,xLo,WHi+2*WSZ,WLo+2*WSZ,2,0, DtF,DtHi,DtLo);
    proj_kernel<<<pgrid,thr,DSMEM>>>(xHi,xLo,WHi+3*WSZ,WLo+3*WSZ,2,64,DtF,DtHi,DtLo);
    proj_kernel<<<pgrid,thr,DSMEM>>>(xHi,xLo,WHi+4*WSZ,WLo+4*WSZ,3,0, VT,nullptr,nullptr);

    scores_kernel<<<dim3(8,8,NBH),thr,DSMEM>>>(QHi,QLo,KHi,KLo,S);
    softmax_rows_kernel<<<NBH*Tn,256>>>(S,AHi,ALo);

    dim3 ggrid(8,NBH);
    prop_kernel<<<ggrid,thr,DSMEM>>>(DtHi,DtLo,DtF,AHi,ALo,DtF+DTSZ,DtHi+DTSZ,DtLo+DTSZ,lam);
    prop_kernel<<<ggrid,thr,DSMEM>>>(DtHi+DTSZ,DtLo+DTSZ,DtF+DTSZ,AHi,ALo,DtF,DtHi,DtLo,lam);
    prop_kernel<<<ggrid,thr,DSMEM>>>(DtHi,DtLo,DtF,AHi,ALo,DtF+DTSZ,DtHi+DTSZ,DtLo+DTSZ,lam);

    readout_kernel<<<NBH,256>>>(DtF+DTSZ,VT,gateT,gvT);
    gather_kernel<<<dim3(32,2,NBH),256>>>(gvT,gateT,gvHi,gvLo,gate_dst);

    proj_kernel<<<pgrid,thr,DSMEM>>>(gvHi,gvLo,WHi+5*WSZ,WLo+5*WSZ,0,0,out,nullptr,nullptr);
}

// round 7
// speedup vs baseline: 3.9429x; 1.0385x over previous
#include <cuda_runtime.h>
#include <cuda_bf16.h>
#include <math.h>
#include <stdint.h>

constexpr int Bn=4, Tn=1024, DMn=1024, Hn=16, DKn=64;
constexpr int BT=Bn*Tn, PLANE=BT*DMn, NBH=Bn*Hn;
constexpr size_t SSZ=(size_t)NBH*Tn*Tn;
constexpr int DT_BH=128*Tn, VT_BH=64*Tn;
constexpr int DSMEM=81920;             // gemm128: 2 stages x (4 planes x 128 x 80B)
constexpr int PSZ=128*80, STG=4*PSZ;
// scores smem: Stile 32x1032 f32 (132096) + Q hi/lo (2x4608) + K hi/lo (2x36864)
constexpr int SC_STILE=0, SC_Q=132096, SC_K=141312, SC_SMEM=215040;
constexpr int QPL=4608, KPL=36864;     // plane sizes, stride 144B

// ---- scratch ----
__device__ __nv_bfloat16 g_xHi[PLANE], g_xLo[PLANE];
__device__ __nv_bfloat16 g_WHi[6][DMn*DMn], g_WLo[6][DMn*DMn];   // W^T split [n][k]
__device__ __nv_bfloat16 g_QHi[PLANE], g_QLo[PLANE], g_KHi[PLANE], g_KLo[PLANE];
__device__ __nv_bfloat16 g_AHi[SSZ], g_ALo[SSZ];
__device__ float        g_DtF [2][(size_t)NBH*DT_BH];
__device__ __nv_bfloat16 g_DtHi[2][(size_t)NBH*DT_BH], g_DtLo[2][(size_t)NBH*DT_BH];
__device__ float g_VT[(size_t)NBH*VT_BH], g_gvT[(size_t)NBH*VT_BH], g_gateT[(size_t)NBH*VT_BH];
__device__ __nv_bfloat16 g_gvHi[PLANE], g_gvLo[PLANE];
__device__ float g_gateS[(size_t)NBH*Tn*DKn];

// ---- helpers ----
__device__ __forceinline__ uint32_t smem_u32(const void* p){
    uint32_t a; asm("{ .reg .u64 t; cvta.to.shared.u64 t, %1; cvt.u32.u64 %0, t; }":"=r"(a):"l"(p)); return a;
}
__device__ __forceinline__ void cp16(uint32_t s, const void* g){
    asm volatile("cp.async.cg.shared.global [%0], [%1], 16;"::"r"(s),"l"(__cvta_generic_to_global(g)):"memory");
}
#define CP_COMMIT() asm volatile("cp.async.commit_group;":::"memory")
#define CP_WAIT1()  asm volatile("cp.async.wait_group 1;":::"memory")
#define CP_WAIT0()  asm volatile("cp.async.wait_group 0;":::"memory")
#define LDM_X4(r,a) asm volatile("ldmatrix.sync.aligned.m8n8.x4.shared.b16 {%0,%1,%2,%3}, [%4];" \
    : "=r"((r)[0]),"=r"((r)[1]),"=r"((r)[2]),"=r"((r)[3]) : "r"(a))
__device__ __forceinline__ void mma16816(float* c, const uint32_t* a, uint32_t b0, uint32_t b1){
    asm volatile("mma.sync.aligned.m16n8k16.row.col.f32.bf16.bf16.f32 "
        "{%0,%1,%2,%3}, {%4,%5,%6,%7}, {%8,%9}, {%0,%1,%2,%3};"
        : "+f"(c[0]),"+f"(c[1]),"+f"(c[2]),"+f"(c[3])
        : "r"(a[0]),"r"(a[1]),"r"(a[2]),"r"(a[3]),"r"(b0),"r"(b1));
}

// ---- gemm128: 128x128 tile, 256 thr, 2-stage cp.async (round-4 proven core) ----
__device__ __forceinline__ void load_plane(uint32_t s, const __nv_bfloat16* g, int ld, int tid){
#pragma unroll
    for(int i=0;i<2;i++){
        int idx=tid+(i<<8), row=idx>>2, seg=idx&3;
        cp16(s+row*80+seg*16, g+(size_t)row*ld+seg*8);
    }
}
__device__ __forceinline__ void load_chunk(uint32_t sb,
    const __nv_bfloat16* aHi,const __nv_bfloat16* aLo,int lda,
    const __nv_bfloat16* bHi,const __nv_bfloat16* bLo,int ldb,int c,int tid){
    size_t ko=(size_t)c*32;
    load_plane(sb,        aHi+ko, lda, tid);
    load_plane(sb+PSZ,    aLo+ko, lda, tid);
    load_plane(sb+2*PSZ,  bHi+ko, ldb, tid);
    load_plane(sb+3*PSZ,  bLo+ko, ldb, tid);
}
__device__ __forceinline__ void compute_stage(uint32_t sb,int wm,int wn,int lane,float acc[2][8][4]){
#pragma unroll
    for(int kk=0;kk<32;kk+=16){
        uint32_t a_hi[2][4], a_lo[2][4];
#pragma unroll
        for(int mi=0;mi<2;mi++){
            uint32_t ad=sb+(uint32_t)((wm*32+mi*16+(lane&15))*80+(kk+((lane>>4)<<3))*2);
            LDM_X4(a_hi[mi],ad); LDM_X4(a_lo[mi],ad+PSZ);
        }
#pragma unroll
        for(int np=0;np<4;np++){
            uint32_t bd=sb+2*PSZ+(uint32_t)((wn*64+np*16+(lane&7)+((lane>>4)<<3))*80+(kk+((lane>>3)&1)*8)*2);
            uint32_t bh[4], bl[4];
            LDM_X4(bh,bd); LDM_X4(bl,bd+PSZ);
#pragma unroll
            for(int mi=0;mi<2;mi++)
#pragma unroll
                for(int j=0;j<2;j++){
                    float* c=acc[mi][np*2+j];
                    mma16816(c,a_hi[mi],bh[2*j],bh[2*j+1]);
                    mma16816(c,a_hi[mi],bl[2*j],bl[2*j+1]);
                    mma16816(c,a_lo[mi],bh[2*j],bh[2*j+1]);
                }
        }
    }
}
__device__ __forceinline__ void gemm128(uint32_t dsm_u32,
    const __nv_bfloat16* aHi,const __nv_bfloat16* aLo,int lda,
    const __nv_bfloat16* bHi,const __nv_bfloat16* bLo,int ldb,
    int nchunks, float acc[2][8][4]){
    int tid=threadIdx.x, lane=tid&31, wid=tid>>5, wm=wid>>1, wn=wid&1;
    load_chunk(dsm_u32, aHi,aLo,lda, bHi,bLo,ldb, 0, tid); CP_COMMIT();
    for(int c=0;c<nchunks;c++){
        if(c+1<nchunks){
            load_chunk(dsm_u32+((c+1)&1)*STG, aHi,aLo,lda, bHi,bLo,ldb, c+1, tid);
            CP_COMMIT(); CP_WAIT1();
        } else CP_WAIT0();
        __syncthreads();
        compute_stage(dsm_u32+(c&1)*STG, wm, wn, lane, acc);
        __syncthreads();
    }
}

// ---- fused projections: z selects weight + output mode ----
__global__ void __launch_bounds__(256,2)
proj_all_kernel(const __nv_bfloat16* __restrict__ aHi,const __nv_bfloat16* __restrict__ aLo,
                int zbase, float* __restrict__ outF){
    extern __shared__ char dsm[];
    int z=blockIdx.z+zbase;
    const __nv_bfloat16* wHi=&g_WHi[z][0];
    const __nv_bfloat16* wLo=&g_WLo[z][0];
    float acc[2][8][4]={};
    int m0=blockIdx.y*128, n0=blockIdx.x*128;
    gemm128(smem_u32(dsm), aHi+(size_t)m0*1024, aLo+(size_t)m0*1024,1024,
            wHi+(size_t)n0*1024, wLo+(size_t)n0*1024,1024, 32, acc);
    int tid=threadIdx.x, lane=tid&31, wid=tid>>5, wm=wid>>1, wn=wid&1, g=lane>>2, tg=lane&3;
    int mode = (z<2)?1 : (z<4)?2 : (z==4)?3 : 0;
    int rowoff = (z==3)?64:0;
    __nv_bfloat16 *oHi=nullptr,*oLo=nullptr; float* oF=nullptr;
    if(z==0){ oHi=g_QHi; oLo=g_QLo; }
    else if(z==1){ oHi=g_KHi; oLo=g_KLo; }
    else if(z<4){ oF=&g_DtF[0][0]; oHi=&g_DtHi[0][0]; oLo=&g_DtLo[0][0]; }
    else if(z==4){ oF=g_VT; }
    else { oF=outF; }
#pragma unroll
    for(int mi=0;mi<2;mi++)
#pragma unroll
    for(int ni=0;ni<8;ni++){
        float* a4=acc[mi][ni];
        int cl=n0+wn*64+ni*8+tg*2;
#pragma unroll
        for(int p=0;p<2;p++){
            int row=m0+wm*32+mi*16+g+p*8;
            float v0=a4[2*p], v1=a4[2*p+1];
            if(mode==0){
                *(float2*)&oF[(size_t)row*1024+cl]=make_float2(v0,v1);
            } else if(mode==1){
                size_t dst=(size_t)row*1024+cl;
                __nv_bfloat16 h0=__float2bfloat16(v0), h1=__float2bfloat16(v1);
                *(__nv_bfloat162*)&oHi[dst]=__nv_bfloat162(h0,h1);
                *(__nv_bfloat162*)&oLo[dst]=__nv_bfloat162(
                    __float2bfloat16(v0-__bfloat162float(h0)),
                    __float2bfloat16(v1-__bfloat162float(h1)));
            } else {
                int b=row>>10, t=row&1023, h=cl>>6, d=cl&63, bh=b*16+h;
                if(mode==2){
                    size_t o0=(size_t)bh*DT_BH+(size_t)(rowoff+d)*1024+t;
                    oF[o0]=v0; oF[o0+1024]=v1;
                    __nv_bfloat16 h0=__float2bfloat16(v0), h1=__float2bfloat16(v1);
                    oHi[o0]=h0; oHi[o0+1024]=h1;
                    oLo[o0]=__float2bfloat16(v0-__bfloat162float(h0));
                    oLo[o0+1024]=__float2bfloat16(v1-__bfloat162float(h1));
                } else {
                    size_t o0=(size_t)bh*VT_BH+(size_t)d*1024+t;
                    oF[o0]=v0; oF[o0+1024]=v1;
                }
            }
        }
    }
}

// ---- fused scores + softmax: block = 32 rows x full 1024 cols of one head ----
// 512 threads = 16 warps (2m x 8n); 4 passes of 256 cols; Stile fp32 in smem.
__global__ void __launch_bounds__(512,1)
scores_softmax_kernel(){
    extern __shared__ char dsm[];
    float* Stile=(float*)(dsm+SC_STILE);           // [32][1032]
    uint32_t qoff=smem_u32(dsm)+SC_Q, koff=smem_u32(dsm)+SC_K;
    int tid=threadIdx.x, lane=tid&31, wid=tid>>5;
    int wm=wid>>3, wn=wid&7;
    int m0=blockIdx.x*32, bh=blockIdx.y, b=bh>>4, h=bh&15;
    size_t qg=(size_t)(b*1024+m0)*1024+h*64;
    size_t kg=(size_t)(b*1024)*1024+h*64;

    // load Q tile (32 rows x 64 bf16 hi+lo = 2 planes x 32 rows x 8 segs = 512 cp16)
    {
        int p=tid>>8, i=tid&255, row=i>>3, seg=i&7;
        const __nv_bfloat16* src=(p? g_QLo:g_QHi)+qg+(size_t)row*1024+seg*8;
        cp16(qoff+p*QPL+row*144+seg*16, src);
    }
    CP_COMMIT();

    for(int np=0;np<4;np++){
        // load K rows [np*256, +256) hi+lo = 2 planes x 256 rows x 8 segs = 4096 cp16
#pragma unroll
        for(int j=0;j<8;j++){
            int idx=tid+j*512, p=idx>>11, i=idx&2047, row=i>>3, seg=i&7;
            const __nv_bfloat16* src=(p? g_KLo:g_KHi)+kg+(size_t)(np*256+row)*1024+seg*8;
            cp16(koff+p*KPL+row*144+seg*16, src);
        }
        CP_COMMIT(); CP_WAIT0();
        __syncthreads();
        float acc[4][4]={};
#pragma unroll
        for(int kk=0;kk<64;kk+=16){
            uint32_t ah[4], al[4];
            uint32_t ad=qoff+(uint32_t)((wm*16+(lane&15))*144+(kk+((lane>>4)<<3))*2);
            LDM_X4(ah,ad); LDM_X4(al,ad+QPL);
#pragma unroll
            for(int nb=0;nb<2;nb++){
                uint32_t bd=koff+(uint32_t)((wn*32+nb*16+(lane&7)+((lane>>4)<<3))*144+(kk+((lane>>3)&1)*8)*2);
                uint32_t bh4[4], bl4[4];
                LDM_X4(bh4,bd); LDM_X4(bl4,bd+KPL);
#pragma unroll
                for(int j=0;j<2;j++){
                    float* c=acc[nb*2+j];
                    mma16816(c,ah,bh4[2*j],bh4[2*j+1]);
                    mma16816(c,ah,bl4[2*j],bl4[2*j+1]);
                    mma16816(c,al,bh4[2*j],bh4[2*j+1]);
                }
            }
        }
        // write pass tile into Stile (scaled)
        int cb=np*256+wn*32;
        int g=lane>>2, tg=lane&3;
#pragma unroll
        for(int nf=0;nf<4;nf++){
#pragma unroll
            for(int p=0;p<2;p++){
                int r=wm*16+g+p*8, c=cb+nf*8+tg*2;
                Stile[r*1032+c]  =acc[nf][2*p]  *0.125f;
                Stile[r*1032+c+1]=acc[nf][2*p+1]*0.125f;
            }
        }
        __syncthreads();
    }

    // softmax: each warp handles 2 rows
    for(int rr=0;rr<2;rr++){
        int r=wid*2+rr;
        float* row=&Stile[r*1032];
        float mx=-1e30f;
        for(int c=lane;c<1024;c+=32) mx=fmaxf(mx,row[c]);
#pragma unroll
        for(int o=16;o;o>>=1) mx=fmaxf(mx,__shfl_xor_sync(0xffffffffu,mx,o));
        float s=0.f;
        for(int c=lane;c<1024;c+=32){ float e=expf(row[c]-mx); row[c]=e; s+=e; }
#pragma unroll
        for(int o=16;o;o>>=1) s+=__shfl_xor_sync(0xffffffffu,s,o);
        float inv=1.f/s;
        size_t ob=((size_t)bh<<20)+(size_t)(m0+r)*1024;
        for(int c=lane;c<1024;c+=32){
            float a=row[c]*inv; __nv_bfloat16 hh=__float2bfloat16(a);
            g_AHi[ob+c]=hh; g_ALo[ob+c]=__float2bfloat16(a-__bfloat162float(hh));
        }
    }
}

// ---- propagation: Dt_out=(1-lam)Dt_in + lam*(Dt_in@A^T) ----
__global__ void __launch_bounds__(256,2)
prop_kernel(const __nv_bfloat16* __restrict__ dHi,const __nv_bfloat16* __restrict__ dLo,
            const float* __restrict__ dF,
            float* __restrict__ outF,__nv_bfloat16* __restrict__ outHi,__nv_bfloat16* __restrict__ outLo,
            const float* __restrict__ lam_ptr){
    extern __shared__ char dsm[];
    float acc[2][8][4]={};
    int n0=blockIdx.x*128, bh=blockIdx.y;
    size_t ab=(size_t)bh*DT_BH, bb=((size_t)bh<<20)+(size_t)n0*1024;
    gemm128(smem_u32(dsm), dHi+ab,dLo+ab,1024, g_AHi+bb,g_ALo+bb,1024, 32, acc);
    float lam=1.f/(1.f+expf(-lam_ptr[0])), oml=1.f-lam;
    int tid=threadIdx.x, lane=tid&31, wid=tid>>5, wm=wid>>1, wn=wid&1, g=lane>>2, tg=lane&3;
#pragma unroll
    for(int mi=0;mi<2;mi++)
#pragma unroll
    for(int ni=0;ni<8;ni++){
        float* a4=acc[mi][ni];
        int cl=n0+wn*64+ni*8+tg*2;
#pragma unroll
        for(int p=0;p<2;p++){
            int r=wm*32+mi*16+g+p*8;
            size_t off=ab+(size_t)r*1024+cl;
            float2 din=*(const float2*)&dF[off];
            float v0=oml*din.x+lam*a4[2*p], v1=oml*din.y+lam*a4[2*p+1];
            *(float2*)&outF[off]=make_float2(v0,v1);
            __nv_bfloat16 h0=__float2bfloat16(v0), h1=__float2bfloat16(v1);
            *(__nv_bfloat162*)&outHi[off]=__nv_bfloat162(h0,h1);
            *(__nv_bfloat162*)&outLo[off]=__nv_bfloat162(
                __float2bfloat16(v0-__bfloat162float(h0)),
                __float2bfloat16(v1-__bfloat162float(h1)));
        }
    }
}

// ---- readout ----
__global__ void __launch_bounds__(256)
readout_kernel(const float* __restrict__ DtF,const float* __restrict__ VT,
               float* __restrict__ gateT,float* __restrict__ gvT){
    int bh=blockIdx.x, w=threadIdx.x>>5, lane=threadIdx.x&31;
    const float* base=DtF+(size_t)bh*DT_BH;
    const float* vb=VT+(size_t)bh*VT_BH;
    for(int j=0;j<8;j++){
        int d=w*8+j;
        const float* rRe=base+(size_t)d*1024;
        const float* rIm=base+(size_t)(64+d)*1024;
        float sre=0.f,sim=0.f;
        for(int t=lane;t<1024;t+=32){ sre+=rRe[t]; sim+=rIm[t]; }
#pragma unroll
        for(int o=16;o;o>>=1){ sre+=__shfl_xor_sync(0xffffffffu,sre,o); sim+=__shfl_xor_sync(0xffffffffu,sim,o); }
        float mre=sre*(1.f/1024.f), mim=sim*(1.f/1024.f);
        float mn=sqrtf(mre*mre+mim*mim);
        float mx=-1e30f;
        for(int t=lane;t<1024;t+=32){
            float re=rRe[t], im=rIm[t];
            mx=fmaxf(mx,(re*mre+im*mim)/(sqrtf(re*re+im*im)*mn+1e-8f));
        }
#pragma unroll
        for(int o=16;o;o>>=1) mx=fmaxf(mx,__shfl_xor_sync(0xffffffffu,mx,o));
        float ss=0.f;
        for(int t=lane;t<1024;t+=32){
            float re=rRe[t], im=rIm[t];
            ss+=expf((re*mre+im*mim)/(sqrtf(re*re+im*im)*mn+1e-8f)-mx);
        }
#pragma unroll
        for(int o=16;o;o>>=1) ss+=__shfl_xor_sync(0xffffffffu,ss,o);
        float inv=1.f/ss;
        size_t ob=(size_t)bh*VT_BH+(size_t)d*1024;
        for(int t=lane;t<1024;t+=32){
            float re=rRe[t], im=rIm[t];
            float gt=expf((re*mre+im*mim)/(sqrtf(re*re+im*im)*mn+1e-8f)-mx)*inv;
            gateT[ob+t]=gt; gvT[ob+t]=gt*vb[(size_t)d*1024+t];
        }
    }
}

// ---- gather ----
__global__ void gather_kernel(const float* __restrict__ gvT,const float* __restrict__ gateT,
                              float* __restrict__ gate){
    __shared__ float tv[32][33], tg2[32][33];
    int bh=blockIdx.z, b=bh>>4, h=bh&15;
    int t0=blockIdx.x*32, d0=blockIdx.y*32;
    int lx=threadIdx.x&31, ly=threadIdx.x>>5;
    for(int i=0;i<32;i+=8){
        size_t src=(size_t)bh*VT_BH+(size_t)(d0+ly+i)*1024+t0+lx;
        tv[ly+i][lx]=gvT[src]; tg2[ly+i][lx]=gateT[src];
    }
    __syncthreads();
    for(int i=0;i<32;i+=8){
        int t=t0+ly+i;
        float v=tv[lx][ly+i], gg=tg2[lx][ly+i];
        size_t po=(size_t)(b*1024+t)*1024+h*64+d0+lx;
        __nv_bfloat16 hh=__float2bfloat16(v);
        g_gvHi[po]=hh; g_gvLo[po]=__float2bfloat16(v-__bfloat162float(hh));
        gate[((size_t)bh*1024+t)*64+d0+lx]=gg;
    }
}

// ---- fused splits: z=0 x elementwise; z=1..6 W^T transpose split ----
__global__ void splits_all_kernel(const float* __restrict__ x,
    const float* __restrict__ W0,const float* __restrict__ W1,const float* __restrict__ W2,
    const float* __restrict__ W3,const float* __restrict__ W4,const float* __restrict__ W5){
    int z=blockIdx.z;
    if(z==0){
        int i=blockIdx.x*256+threadIdx.x;
        for(; i<PLANE; i+=1024*256){
            float v=x[i]; __nv_bfloat16 h=__float2bfloat16(v);
            g_xHi[i]=h; g_xLo[i]=__float2bfloat16(v-__bfloat162float(h));
        }
        return;
    }
    const float* Ws[6]={W0,W1,W2,W3,W4,W5};
    int w=z-1;
    const float* W=Ws[w];
    __nv_bfloat16* hi=&g_WHi[w][0]; __nv_bfloat16* lo=&g_WLo[w][0];
    __shared__ float ts[32][33];
    int k0=(blockIdx.x>>5)*32, n0=(blockIdx.x&31)*32;
    int lx=threadIdx.x&31, ly=threadIdx.x>>5;
    for(int i=0;i<32;i+=8) ts[ly+i][lx]=W[(size_t)(k0+ly+i)*1024+n0+lx];
    __syncthreads();
    for(int i=0;i<32;i+=8){
        float v=ts[lx][ly+i];
        size_t dst=(size_t)(n0+ly+i)*1024+k0+lx;
        __nv_bfloat16 h=__float2bfloat16(v);
        hi[dst]=h; lo[dst]=__float2bfloat16(v-__bfloat162float(h));
    }
}

extern "C" void kernel_launch(void* const* d_in,const int* in_sizes,int n_in,
                              void* d_out,int out_size){
    const float* x=(const float*)d_in[0];
    const float* lam=(const float*)d_in[7];

    __nv_bfloat16 *xHi,*xLo,*DtHi,*DtLo,*gvHi,*gvLo;
    float *DtF,*VT,*gvT,*gateT,*gateS;
    cudaGetSymbolAddress((void**)&xHi,g_xHi);   cudaGetSymbolAddress((void**)&xLo,g_xLo);
    cudaGetSymbolAddress((void**)&DtF,g_DtF);   cudaGetSymbolAddress((void**)&DtHi,g_DtHi);
    cudaGetSymbolAddress((void**)&DtLo,g_DtLo);
    cudaGetSymbolAddress((void**)&VT,g_VT);     cudaGetSymbolAddress((void**)&gvT,g_gvT);
    cudaGetSymbolAddress((void**)&gateT,g_gateT);
    cudaGetSymbolAddress((void**)&gvHi,g_gvHi); cudaGetSymbolAddress((void**)&gvLo,g_gvLo);
    cudaGetSymbolAddress((void**)&gateS,g_gateS);

    const size_t DTSZ=(size_t)NBH*DT_BH;
    float* out=(float*)d_out;
    float* gate_dst=(out_size>=2*PLANE)? out+PLANE : gateS;

    cudaFuncSetAttribute(proj_all_kernel,      cudaFuncAttributeMaxDynamicSharedMemorySize,DSMEM);
    cudaFuncSetAttribute(prop_kernel,          cudaFuncAttributeMaxDynamicSharedMemorySize,DSMEM);
    cudaFuncSetAttribute(scores_softmax_kernel,cudaFuncAttributeMaxDynamicSharedMemorySize,SC_SMEM);

    // 1: all splits
    splits_all_kernel<<<dim3(1024,1,7),256>>>(x,(const float*)d_in[1],(const float*)d_in[2],
        (const float*)d_in[3],(const float*)d_in[4],(const float*)d_in[5],(const float*)d_in[6]);
    // 2: all 5 input projections
    proj_all_kernel<<<dim3(8,32,5),256,DSMEM>>>(xHi,xLo,0,nullptr);
    // 3: fused scores + softmax -> adjacency hi/lo
    scores_softmax_kernel<<<dim3(32,NBH),512,SC_SMEM>>>();
    // 4-6: propagation (ncu -s 5 captures launch 6 = prop #3)
    dim3 ggrid(8,NBH), thr(256);
    prop_kernel<<<ggrid,thr,DSMEM>>>(DtHi,DtLo,DtF,DtF+DTSZ,DtHi+DTSZ,DtLo+DTSZ,lam);
    prop_kernel<<<ggrid,thr,DSMEM>>>(DtHi+DTSZ,DtLo+DTSZ,DtF+DTSZ,DtF,DtHi,DtLo,lam);
    prop_kernel<<<ggrid,thr,DSMEM>>>(DtHi,DtLo,DtF,DtF+DTSZ,DtHi+DTSZ,DtLo+DTSZ,lam);
    // 7: readout, 8: gather
    readout_kernel<<<NBH,256>>>(DtF+DTSZ,VT,gateT,gvT);
    gather_kernel<<<dim3(32,2,NBH),256>>>(gvT,gateT,gate_dst);
    // 9: output projection
    proj_all_kernel<<<dim3(8,32,1),256,DSMEM>>>(gvHi,gvLo,5,out);
}